// round 14
// baseline (speedup 1.0000x reference)
#include <cuda_runtime.h>
#include <cstdint>

// Problem constants: x is [64,3,224,224] f32, out is [16,64,3,224,224] f32.
#define NELEM    9633792      // 64*3*224*224
#define HWPLANE  50176        // 224*224
#define TSTEPS   16
#define EPT      4            // elements per thread (float4 granularity)

// ---------------------------------------------------------------------------
// Compile-time key schedule: keys[t] = threefry2x32((0,1), (0,t)) under the
// partitionable split, with the 6 key-injection constants pre-folded.
// ---------------------------------------------------------------------------
struct Keys { unsigned a0,b0,a1,b1,a2,b2,a3,b3,a4,b4,a5,b5; };

__host__ __device__ constexpr unsigned rotlc(unsigned v, int r) {
    return (v << r) | (v >> (32 - r));
}

__host__ __device__ constexpr Keys make_keys(int t) {
    const unsigned k0 = 0u, k1 = 1u;
    const unsigned k2 = k0 ^ k1 ^ 0x1BD11BDAu;
    unsigned x0 = k0;                 // c0 = 0
    unsigned x1 = (unsigned)t + k1;   // c1 = t
    x0+=x1; x1=rotlc(x1,13); x1^=x0;
    x0+=x1; x1=rotlc(x1,15); x1^=x0;
    x0+=x1; x1=rotlc(x1,26); x1^=x0;
    x0+=x1; x1=rotlc(x1, 6); x1^=x0;
    x0+=k1; x1+=k2+1u;
    x0+=x1; x1=rotlc(x1,17); x1^=x0;
    x0+=x1; x1=rotlc(x1,29); x1^=x0;
    x0+=x1; x1=rotlc(x1,16); x1^=x0;
    x0+=x1; x1=rotlc(x1,24); x1^=x0;
    x0+=k2; x1+=k0+2u;
    x0+=x1; x1=rotlc(x1,13); x1^=x0;
    x0+=x1; x1=rotlc(x1,15); x1^=x0;
    x0+=x1; x1=rotlc(x1,26); x1^=x0;
    x0+=x1; x1=rotlc(x1, 6); x1^=x0;
    x0+=k0; x1+=k1+3u;
    x0+=x1; x1=rotlc(x1,17); x1^=x0;
    x0+=x1; x1=rotlc(x1,29); x1^=x0;
    x0+=x1; x1=rotlc(x1,16); x1^=x0;
    x0+=x1; x1=rotlc(x1,24); x1^=x0;
    x0+=k1; x1+=k2+4u;
    x0+=x1; x1=rotlc(x1,13); x1^=x0;
    x0+=x1; x1=rotlc(x1,15); x1^=x0;
    x0+=x1; x1=rotlc(x1,26); x1^=x0;
    x0+=x1; x1=rotlc(x1, 6); x1^=x0;
    x0+=k2; x1+=k0+5u;
    const unsigned K0 = x0, K1 = x1, K2 = K0 ^ K1 ^ 0x1BD11BDAu;
    return Keys{K0,K1, K1,K2+1u, K2,K0+2u, K0,K1+3u, K1,K2+4u, K2,K0+5u};
}

// ---------------------------------------------------------------------------
// FMA-pipe integer adds. 'one' (==1) comes from a kernel parameter, so ptxas
// cannot strength-reduce the IMAD forms back to IADD3.
// ---------------------------------------------------------------------------
__device__ __forceinline__ unsigned addf(unsigned a, unsigned b, unsigned one) {
    unsigned d;
    asm("mad.lo.u32 %0, %1, %2, %3;" : "=r"(d) : "r"(a), "r"(one), "r"(b));
    return d;
}

template<unsigned IMM>
__device__ __forceinline__ unsigned addimm(unsigned x, unsigned one) {
    unsigned d;
    asm("mad.lo.u32 %0, %1, %2, %3;" : "=r"(d) : "r"(one), "n"(IMM), "r"(x));
    return d;
}

// (bits >> 9) | 0x3f800000 as one op: hi32(bits * 2^23) + 0x3f800000
// (disjoint bit ranges, so OR == ADD). fma pipe (has headroom).
__device__ __forceinline__ unsigned ubits(unsigned bits, unsigned c23) {
    unsigned d;
    asm("mad.hi.u32 %0, %1, %2, %3;" : "=r"(d) : "r"(bits), "r"(c23),
        "n"(0x3f800000));
    return d;
}

// ---------------------------------------------------------------------------
// threefry2x32 (JAX-exact 20 rounds) with all key material as immediates.
// Returns o0 ^ o1 (partitionable bits fold).
// ---------------------------------------------------------------------------
template<unsigned A0,unsigned B0,unsigned A1,unsigned B1,unsigned A2,unsigned B2,
         unsigned A3,unsigned B3,unsigned A4,unsigned B4,unsigned A5,unsigned B5>
__device__ __forceinline__ unsigned tf_bits(unsigned c1, unsigned one) {
    unsigned x1 = addimm<B0>(c1, one);
    unsigned x0 = addimm<A0>(x1, one);   // round-1 add folded with x0 init
    x1 = __funnelshift_l(x1, x1, 13); x1 ^= x0;
#define TFR(r) { x0 = addf(x1, x0, one); \
                 x1 = __funnelshift_l(x1, x1, (r)); x1 ^= x0; }
    TFR(15) TFR(26) TFR(6)
    x0 = addimm<A1>(x0, one); x1 = addimm<B1>(x1, one);
    TFR(17) TFR(29) TFR(16) TFR(24)
    x0 = addimm<A2>(x0, one); x1 = addimm<B2>(x1, one);
    TFR(13) TFR(15) TFR(26) TFR(6)
    x0 = addimm<A3>(x0, one); x1 = addimm<B3>(x1, one);
    TFR(17) TFR(29) TFR(16) TFR(24)
    x0 = addimm<A4>(x0, one); x1 = addimm<B4>(x1, one);
    TFR(13) TFR(15) TFR(26) TFR(6)
    x0 = addimm<A5>(x0, one); x1 = addimm<B5>(x1, one);
#undef TFR
    return x0 ^ x1;
}

// ---------------------------------------------------------------------------
// All-FMA-pipe clampless Bernoulli tail (zero alu ops):
//   d      = u - p               (FADD; sign(d)=1 <=> u < p, Sterbenz-exact
//                                 near equality, non-ftz preserves subnormal
//                                 signs; u==p -> d=+0 -> no spike, matches <)
//   sign   = hi32(d_bits * two)  (IMAD.HI == d>>31; 'two' opaque)
//   ovalb  = sign*deltab + ov0b  (IMAD; deltab = bits(ov1)-bits(ov0))
//   spikeb = sign * 0x3f800000   (IMAD; non-pow2 imm stays IMAD)
//   rem   -= as_float(spikeb)    (FADD, exact; clampless per R12 validation)
// ---------------------------------------------------------------------------
__device__ __forceinline__ float bern_tail(float& rem, float u, float p,
                                           unsigned ov0b, unsigned deltab,
                                           unsigned two) {
    float d = __fadd_rn(u, -p);
    unsigned sign, ovalb, spikeb;
    asm("mad.hi.u32 %0, %1, %2, 0;" : "=r"(sign)
        : "r"(__float_as_uint(d)), "r"(two));
    asm("mad.lo.u32 %0, %1, %2, %3;" : "=r"(ovalb)
        : "r"(sign), "r"(deltab), "r"(ov0b));
    asm("mul.lo.u32 %0, %1, %2;" : "=r"(spikeb)
        : "r"(sign), "n"(0x3f800000));
    rem = __fadd_rn(rem, -__uint_as_float(spikeb));
    return __uint_as_float(ovalb);
}

// Last step: rem is dead, only the output select.
__device__ __forceinline__ float bern_last(float u, float p,
                                           unsigned ov0b, unsigned deltab,
                                           unsigned two) {
    float d = __fadd_rn(u, -p);
    unsigned sign, ovalb;
    asm("mad.hi.u32 %0, %1, %2, 0;" : "=r"(sign)
        : "r"(__float_as_uint(d)), "r"(two));
    asm("mad.lo.u32 %0, %1, %2, %3;" : "=r"(ovalb)
        : "r"(sign), "r"(deltab), "r"(ov0b));
    return __uint_as_float(ovalb);
}

// ---------------------------------------------------------------------------
// One fully specialized time step for 4 elements. The 4 threefry blocks are
// computed first (independent chains), then the float tail.
// ---------------------------------------------------------------------------
template<int T>
__device__ __forceinline__ void do_step(float rem[EPT], unsigned j,
                                        unsigned ov0b, unsigned deltab,
                                        unsigned one, unsigned c23,
                                        unsigned two,
                                        float* __restrict__ out)
{
    constexpr int   S    = TSTEPS - T;            // remaining slots
    constexpr float SF   = (float)S;
    constexpr float INV  = 1.0f / SF;             // rn(1/S), exact for pow2
    constexpr bool  POW2 = (S & (S - 1)) == 0;
    constexpr Keys  K    = make_keys(T);

    unsigned bits[EPT];
#pragma unroll
    for (int e = 0; e < EPT; e++) {
        bits[e] = tf_bits<K.a0,K.b0,K.a1,K.b1,K.a2,K.b2,
                          K.a3,K.b3,K.a4,K.b4,K.a5,K.b5>(j + (unsigned)e, one);
    }

    float ovals[EPT];
#pragma unroll
    for (int e = 0; e < EPT; e++) {
        // u = bitcast((bits>>9)|0x3f800000) - 1.0 (exact Sterbenz subtraction)
        const float u = __uint_as_float(ubits(bits[e], c23)) - 1.0f;

        // p = rn(rem/S). Reference's clip(p,0,1) drops out (R12-validated).
        float p;
        if (S == 1) {
            p = rem[e];
        } else if (POW2) {
            p = __fmul_rn(rem[e], INV);
        } else {
            const float q0 = __fmul_rn(rem[e], INV);
            const float r  = __fmaf_rn(-SF, q0, rem[e]);
            p = __fmaf_rn(r, INV, q0);            // Markstein, correctly rounded
        }

        if (S > 1) {
            ovals[e] = bern_tail(rem[e], u, p, ov0b, deltab, two);
        } else {
            ovals[e] = bern_last(u, p, ov0b, deltab, two);
        }
    }

    float4 o;
    o.x = ovals[0]; o.y = ovals[1]; o.z = ovals[2]; o.w = ovals[3];
    // Streaming store: output is write-once, never re-read.
    __stcs(reinterpret_cast<float4*>(out + (size_t)T * NELEM + j), o);
}

// ---------------------------------------------------------------------------
// Main kernel. __launch_bounds__(256, 4): 64-reg budget (proven equal-best).
// Grid covers NELEM exactly, so no bounds guard.
// ---------------------------------------------------------------------------
__global__ void __launch_bounds__(256, 4)
hyper_kernel(const float* __restrict__ x,
             const float* __restrict__ meanv,
             const float* __restrict__ stdv,
             float* __restrict__ out,
             unsigned one, unsigned c23, unsigned two)
{
    const unsigned j = (blockIdx.x * blockDim.x + threadIdx.x) * EPT;

    const unsigned c = (j / HWPLANE) % 3u;
    const float m = meanv[c];
    const float s = stdv[c];
    // Output values for spike=0 and spike=1: (spike - m) / s, IEEE divide.
    const float ov0 = __fdiv_rn(0.0f - m, s);
    const float ov1 = __fdiv_rn(1.0f - m, s);
    const unsigned ov0b   = __float_as_uint(ov0);
    const unsigned deltab = __float_as_uint(ov1) - ov0b;   // bit-delta select

    const float4 xv = *reinterpret_cast<const float4*>(x + j);

    // probs = clip(x*s + m, 0, 1) (separate rn mul + rn add, matching XLA);
    // rem0 = probs * 16 (exact).
    float rem[EPT];
    {
        const float xs[EPT] = {xv.x, xv.y, xv.z, xv.w};
#pragma unroll
        for (int e = 0; e < EPT; e++) {
            float pr = __fadd_rn(__fmul_rn(xs[e], s), m);
            pr = fminf(fmaxf(pr, 0.0f), 1.0f);
            rem[e] = __fmul_rn(pr, 16.0f);
        }
    }

    do_step< 0>(rem, j, ov0b, deltab, one, c23, two, out);
    do_step< 1>(rem, j, ov0b, deltab, one, c23, two, out);
    do_step< 2>(rem, j, ov0b, deltab, one, c23, two, out);
    do_step< 3>(rem, j, ov0b, deltab, one, c23, two, out);
    do_step< 4>(rem, j, ov0b, deltab, one, c23, two, out);
    do_step< 5>(rem, j, ov0b, deltab, one, c23, two, out);
    do_step< 6>(rem, j, ov0b, deltab, one, c23, two, out);
    do_step< 7>(rem, j, ov0b, deltab, one, c23, two, out);
    do_step< 8>(rem, j, ov0b, deltab, one, c23, two, out);
    do_step< 9>(rem, j, ov0b, deltab, one, c23, two, out);
    do_step<10>(rem, j, ov0b, deltab, one, c23, two, out);
    do_step<11>(rem, j, ov0b, deltab, one, c23, two, out);
    do_step<12>(rem, j, ov0b, deltab, one, c23, two, out);
    do_step<13>(rem, j, ov0b, deltab, one, c23, two, out);
    do_step<14>(rem, j, ov0b, deltab, one, c23, two, out);
    do_step<15>(rem, j, ov0b, deltab, one, c23, two, out);
}

// ---------------------------------------------------------------------------
// Launch: single kernel, graph-capturable, allocation-free. The opaque
// 'one'/'c23'/'two' params keep the IMAD forms alive through ptxas.
// ---------------------------------------------------------------------------
extern "C" void kernel_launch(void* const* d_in, const int* in_sizes, int n_in,
                              void* d_out, int out_size) {
    (void)in_sizes; (void)n_in; (void)out_size;

    const float* x  = (const float*)d_in[0];
    const float* mn = (const float*)d_in[1];
    const float* sd = (const float*)d_in[2];
    float* out = (float*)d_out;

    const int threads = 256;
    const int blocks = NELEM / (threads * EPT);   // 9408 exactly
    hyper_kernel<<<blocks, threads>>>(x, mn, sd, out, 1u, 1u << 23, 2u);
}

// round 16
// speedup vs baseline: 1.0093x; 1.0093x over previous
#include <cuda_runtime.h>
#include <cstdint>

// Problem constants: x is [64,3,224,224] f32, out is [16,64,3,224,224] f32.
#define NELEM    9633792      // 64*3*224*224
#define HWPLANE  50176        // 224*224
#define TSTEPS   16
#define EPT      4            // elements per thread (float4 granularity)

// ---------------------------------------------------------------------------
// Compile-time key schedule: keys[t] = threefry2x32((0,1), (0,t)) under the
// partitionable split, with the 6 key-injection constants pre-folded.
// ---------------------------------------------------------------------------
struct Keys { unsigned a0,b0,a1,b1,a2,b2,a3,b3,a4,b4,a5,b5; };

__host__ __device__ constexpr unsigned rotlc(unsigned v, int r) {
    return (v << r) | (v >> (32 - r));
}

__host__ __device__ constexpr Keys make_keys(int t) {
    const unsigned k0 = 0u, k1 = 1u;
    const unsigned k2 = k0 ^ k1 ^ 0x1BD11BDAu;
    unsigned x0 = k0;                 // c0 = 0
    unsigned x1 = (unsigned)t + k1;   // c1 = t
    x0+=x1; x1=rotlc(x1,13); x1^=x0;
    x0+=x1; x1=rotlc(x1,15); x1^=x0;
    x0+=x1; x1=rotlc(x1,26); x1^=x0;
    x0+=x1; x1=rotlc(x1, 6); x1^=x0;
    x0+=k1; x1+=k2+1u;
    x0+=x1; x1=rotlc(x1,17); x1^=x0;
    x0+=x1; x1=rotlc(x1,29); x1^=x0;
    x0+=x1; x1=rotlc(x1,16); x1^=x0;
    x0+=x1; x1=rotlc(x1,24); x1^=x0;
    x0+=k2; x1+=k0+2u;
    x0+=x1; x1=rotlc(x1,13); x1^=x0;
    x0+=x1; x1=rotlc(x1,15); x1^=x0;
    x0+=x1; x1=rotlc(x1,26); x1^=x0;
    x0+=x1; x1=rotlc(x1, 6); x1^=x0;
    x0+=k0; x1+=k1+3u;
    x0+=x1; x1=rotlc(x1,17); x1^=x0;
    x0+=x1; x1=rotlc(x1,29); x1^=x0;
    x0+=x1; x1=rotlc(x1,16); x1^=x0;
    x0+=x1; x1=rotlc(x1,24); x1^=x0;
    x0+=k1; x1+=k2+4u;
    x0+=x1; x1=rotlc(x1,13); x1^=x0;
    x0+=x1; x1=rotlc(x1,15); x1^=x0;
    x0+=x1; x1=rotlc(x1,26); x1^=x0;
    x0+=x1; x1=rotlc(x1, 6); x1^=x0;
    x0+=k2; x1+=k0+5u;
    const unsigned K0 = x0, K1 = x1, K2 = K0 ^ K1 ^ 0x1BD11BDAu;
    return Keys{K0,K1, K1,K2+1u, K2,K0+2u, K0,K1+3u, K1,K2+4u, K2,K0+5u};
}

// ---------------------------------------------------------------------------
// FMA-pipe integer adds. 'one' (==1) comes from a kernel parameter, so ptxas
// cannot strength-reduce the IMAD forms back to IADD3.
// ---------------------------------------------------------------------------
__device__ __forceinline__ unsigned addf(unsigned a, unsigned b, unsigned one) {
    unsigned d;
    asm("mad.lo.u32 %0, %1, %2, %3;" : "=r"(d) : "r"(a), "r"(one), "r"(b));
    return d;
}

template<unsigned IMM>
__device__ __forceinline__ unsigned addimm(unsigned x, unsigned one) {
    unsigned d;
    asm("mad.lo.u32 %0, %1, %2, %3;" : "=r"(d) : "r"(one), "n"(IMM), "r"(x));
    return d;
}

// (bits >> 9) | 0x3f800000 as one op: hi32(bits * 2^23) + 0x3f800000
// (disjoint bit ranges, so OR == ADD). fma pipe (has headroom).
__device__ __forceinline__ unsigned ubits(unsigned bits, unsigned c23) {
    unsigned d;
    asm("mad.hi.u32 %0, %1, %2, %3;" : "=r"(d) : "r"(bits), "r"(c23),
        "n"(0x3f800000));
    return d;
}

// ---------------------------------------------------------------------------
// threefry2x32 (JAX-exact 20 rounds) with all key material as immediates.
// Returns o0 ^ o1 (partitionable bits fold).
// ---------------------------------------------------------------------------
template<unsigned A0,unsigned B0,unsigned A1,unsigned B1,unsigned A2,unsigned B2,
         unsigned A3,unsigned B3,unsigned A4,unsigned B4,unsigned A5,unsigned B5>
__device__ __forceinline__ unsigned tf_bits(unsigned c1, unsigned one) {
    unsigned x1 = addimm<B0>(c1, one);
    unsigned x0 = addimm<A0>(x1, one);   // round-1 add folded with x0 init
    x1 = __funnelshift_l(x1, x1, 13); x1 ^= x0;
#define TFR(r) { x0 = addf(x1, x0, one); \
                 x1 = __funnelshift_l(x1, x1, (r)); x1 ^= x0; }
    TFR(15) TFR(26) TFR(6)
    x0 = addimm<A1>(x0, one); x1 = addimm<B1>(x1, one);
    TFR(17) TFR(29) TFR(16) TFR(24)
    x0 = addimm<A2>(x0, one); x1 = addimm<B2>(x1, one);
    TFR(13) TFR(15) TFR(26) TFR(6)
    x0 = addimm<A3>(x0, one); x1 = addimm<B3>(x1, one);
    TFR(17) TFR(29) TFR(16) TFR(24)
    x0 = addimm<A4>(x0, one); x1 = addimm<B4>(x1, one);
    TFR(13) TFR(15) TFR(26) TFR(6)
    x0 = addimm<A5>(x0, one); x1 = addimm<B5>(x1, one);
#undef TFR
    return x0 ^ x1;
}

// ---------------------------------------------------------------------------
// Clampless predicated Bernoulli tail (R13 idiom, chain-optimized order):
//   setp.lt sp, u, p      — spike decision
//   @sp add rem, rem, -1  — rem update FIRST (the only loop-carried chain)
//   selp    oval          — output select (off the carried chain)
// clip removal validated bit-exactly by R12 (rel_err == 0.0 on full dataset).
// ---------------------------------------------------------------------------
__device__ __forceinline__ float bern_tail(float& rem, float u, float p,
                                           float ov0, float ov1) {
    float oval;
    asm("{\n\t"
        ".reg .pred sp;\n\t"
        "setp.lt.f32 sp, %2, %3;\n\t"
        "@sp add.f32 %1, %1, 0fBF800000;\n\t"    // rem -= 1 (exact), on-chain
        "selp.f32 %0, %4, %5, sp;\n\t"           // oval, off-chain
        "}"
        : "=f"(oval), "+f"(rem)
        : "f"(u), "f"(p), "f"(ov1), "f"(ov0));
    return oval;
}

// ---------------------------------------------------------------------------
// One fully specialized time step for 4 elements. The 4 threefry blocks are
// computed first (independent chains), then the float tail.
// ---------------------------------------------------------------------------
template<int T>
__device__ __forceinline__ void do_step(float rem[EPT], unsigned j,
                                        float ov0, float ov1,
                                        unsigned one, unsigned c23,
                                        float* __restrict__ out)
{
    constexpr int   S    = TSTEPS - T;            // remaining slots
    constexpr float SF   = (float)S;
    constexpr float INV  = 1.0f / SF;             // rn(1/S), exact for pow2
    constexpr bool  POW2 = (S & (S - 1)) == 0;
    constexpr Keys  K    = make_keys(T);

    unsigned bits[EPT];
#pragma unroll
    for (int e = 0; e < EPT; e++) {
        bits[e] = tf_bits<K.a0,K.b0,K.a1,K.b1,K.a2,K.b2,
                          K.a3,K.b3,K.a4,K.b4,K.a5,K.b5>(j + (unsigned)e, one);
    }

    float ovals[EPT];
#pragma unroll
    for (int e = 0; e < EPT; e++) {
        // u = bitcast((bits>>9)|0x3f800000) - 1.0 (exact Sterbenz subtraction)
        const float u = __uint_as_float(ubits(bits[e], c23)) - 1.0f;

        // p = rn(rem/S). Reference's clip(p,0,1) drops out (R12-validated).
        float p;
        if (S == 1) {
            p = rem[e];
        } else if (POW2) {
            p = __fmul_rn(rem[e], INV);
        } else {
            const float q0 = __fmul_rn(rem[e], INV);
            const float r  = __fmaf_rn(-SF, q0, rem[e]);
            p = __fmaf_rn(r, INV, q0);            // Markstein, correctly rounded
        }

        if (S > 1) {
            ovals[e] = bern_tail(rem[e], u, p, ov0, ov1);
        } else {
            ovals[e] = (u < p) ? ov1 : ov0;       // last step: rem is dead
        }
    }

    float4 o;
    o.x = ovals[0]; o.y = ovals[1]; o.z = ovals[2]; o.w = ovals[3];
    // Streaming store: output is write-once, never re-read.
    __stcs(reinterpret_cast<float4*>(out + (size_t)T * NELEM + j), o);
}

// ---------------------------------------------------------------------------
// Main kernel. __launch_bounds__(256, 4): 64-reg budget (proven equal-best).
// Grid covers NELEM exactly, so no bounds guard. R13 structure throughout.
// ---------------------------------------------------------------------------
__global__ void __launch_bounds__(256, 4)
hyper_kernel(const float* __restrict__ x,
             const float* __restrict__ meanv,
             const float* __restrict__ stdv,
             float* __restrict__ out,
             unsigned one, unsigned c23)
{
    const unsigned j = (blockIdx.x * blockDim.x + threadIdx.x) * EPT;

    const unsigned c = (j / HWPLANE) % 3u;
    const float m = meanv[c];
    const float s = stdv[c];
    // Output values for spike=0 and spike=1: (spike - m) / s, IEEE divide.
    const float ov0 = __fdiv_rn(0.0f - m, s);
    const float ov1 = __fdiv_rn(1.0f - m, s);

    const float4 xv = *reinterpret_cast<const float4*>(x + j);

    // probs = clip(x*s + m, 0, 1) (separate rn mul + rn add, matching XLA);
    // rem0 = probs * 16 (exact).
    float rem[EPT];
    {
        const float xs[EPT] = {xv.x, xv.y, xv.z, xv.w};
#pragma unroll
        for (int e = 0; e < EPT; e++) {
            float pr = __fadd_rn(__fmul_rn(xs[e], s), m);
            pr = fminf(fmaxf(pr, 0.0f), 1.0f);
            rem[e] = __fmul_rn(pr, 16.0f);
        }
    }

    do_step< 0>(rem, j, ov0, ov1, one, c23, out);
    do_step< 1>(rem, j, ov0, ov1, one, c23, out);
    do_step< 2>(rem, j, ov0, ov1, one, c23, out);
    do_step< 3>(rem, j, ov0, ov1, one, c23, out);
    do_step< 4>(rem, j, ov0, ov1, one, c23, out);
    do_step< 5>(rem, j, ov0, ov1, one, c23, out);
    do_step< 6>(rem, j, ov0, ov1, one, c23, out);
    do_step< 7>(rem, j, ov0, ov1, one, c23, out);
    do_step< 8>(rem, j, ov0, ov1, one, c23, out);
    do_step< 9>(rem, j, ov0, ov1, one, c23, out);
    do_step<10>(rem, j, ov0, ov1, one, c23, out);
    do_step<11>(rem, j, ov0, ov1, one, c23, out);
    do_step<12>(rem, j, ov0, ov1, one, c23, out);
    do_step<13>(rem, j, ov0, ov1, one, c23, out);
    do_step<14>(rem, j, ov0, ov1, one, c23, out);
    do_step<15>(rem, j, ov0, ov1, one, c23, out);
}

// ---------------------------------------------------------------------------
// Launch: single kernel, graph-capturable, allocation-free. The opaque
// 'one'/'c23' params keep the IMAD forms alive through ptxas.
// ---------------------------------------------------------------------------
extern "C" void kernel_launch(void* const* d_in, const int* in_sizes, int n_in,
                              void* d_out, int out_size) {
    (void)in_sizes; (void)n_in; (void)out_size;

    const float* x  = (const float*)d_in[0];
    const float* mn = (const float*)d_in[1];
    const float* sd = (const float*)d_in[2];
    float* out = (float*)d_out;

    const int threads = 256;
    const int blocks = NELEM / (threads * EPT);   // 9408 exactly
    hyper_kernel<<<blocks, threads>>>(x, mn, sd, out, 1u, 1u << 23);
}

// round 17
// speedup vs baseline: 1.0216x; 1.0121x over previous
#include <cuda_runtime.h>
#include <cstdint>

// Problem constants: x is [64,3,224,224] f32, out is [16,64,3,224,224] f32.
#define NELEM    9633792      // 64*3*224*224
#define HWPLANE  50176        // 224*224
#define TSTEPS   16
#define EPT      4            // elements per thread (float4 granularity)

// ---------------------------------------------------------------------------
// Compile-time key schedule: keys[t] = threefry2x32((0,1), (0,t)) under the
// partitionable split, with the 6 key-injection constants pre-folded.
// ---------------------------------------------------------------------------
struct Keys { unsigned a0,b0,a1,b1,a2,b2,a3,b3,a4,b4,a5,b5; };

__host__ __device__ constexpr unsigned rotlc(unsigned v, int r) {
    return (v << r) | (v >> (32 - r));
}

__host__ __device__ constexpr Keys make_keys(int t) {
    const unsigned k0 = 0u, k1 = 1u;
    const unsigned k2 = k0 ^ k1 ^ 0x1BD11BDAu;
    unsigned x0 = k0;                 // c0 = 0
    unsigned x1 = (unsigned)t + k1;   // c1 = t
    x0+=x1; x1=rotlc(x1,13); x1^=x0;
    x0+=x1; x1=rotlc(x1,15); x1^=x0;
    x0+=x1; x1=rotlc(x1,26); x1^=x0;
    x0+=x1; x1=rotlc(x1, 6); x1^=x0;
    x0+=k1; x1+=k2+1u;
    x0+=x1; x1=rotlc(x1,17); x1^=x0;
    x0+=x1; x1=rotlc(x1,29); x1^=x0;
    x0+=x1; x1=rotlc(x1,16); x1^=x0;
    x0+=x1; x1=rotlc(x1,24); x1^=x0;
    x0+=k2; x1+=k0+2u;
    x0+=x1; x1=rotlc(x1,13); x1^=x0;
    x0+=x1; x1=rotlc(x1,15); x1^=x0;
    x0+=x1; x1=rotlc(x1,26); x1^=x0;
    x0+=x1; x1=rotlc(x1, 6); x1^=x0;
    x0+=k0; x1+=k1+3u;
    x0+=x1; x1=rotlc(x1,17); x1^=x0;
    x0+=x1; x1=rotlc(x1,29); x1^=x0;
    x0+=x1; x1=rotlc(x1,16); x1^=x0;
    x0+=x1; x1=rotlc(x1,24); x1^=x0;
    x0+=k1; x1+=k2+4u;
    x0+=x1; x1=rotlc(x1,13); x1^=x0;
    x0+=x1; x1=rotlc(x1,15); x1^=x0;
    x0+=x1; x1=rotlc(x1,26); x1^=x0;
    x0+=x1; x1=rotlc(x1, 6); x1^=x0;
    x0+=k2; x1+=k0+5u;
    const unsigned K0 = x0, K1 = x1, K2 = K0 ^ K1 ^ 0x1BD11BDAu;
    return Keys{K0,K1, K1,K2+1u, K2,K0+2u, K0,K1+3u, K1,K2+4u, K2,K0+5u};
}

// ---------------------------------------------------------------------------
// FMA-pipe integer adds. 'one' (==1) comes from a kernel parameter, so ptxas
// cannot strength-reduce the IMAD forms back to IADD3.
// ---------------------------------------------------------------------------
__device__ __forceinline__ unsigned addf(unsigned a, unsigned b, unsigned one) {
    unsigned d;
    asm("mad.lo.u32 %0, %1, %2, %3;" : "=r"(d) : "r"(a), "r"(one), "r"(b));
    return d;
}

template<unsigned IMM>
__device__ __forceinline__ unsigned addimm(unsigned x, unsigned one) {
    unsigned d;
    asm("mad.lo.u32 %0, %1, %2, %3;" : "=r"(d) : "r"(one), "n"(IMM), "r"(x));
    return d;
}

// (bits >> 9) | 0x3f800000 as one op: hi32(bits * 2^23) + 0x3f800000
// (disjoint bit ranges, so OR == ADD). fma pipe (has headroom).
__device__ __forceinline__ unsigned ubits(unsigned bits, unsigned c23) {
    unsigned d;
    asm("mad.hi.u32 %0, %1, %2, %3;" : "=r"(d) : "r"(bits), "r"(c23),
        "n"(0x3f800000));
    return d;
}

// ---------------------------------------------------------------------------
// threefry2x32 (JAX-exact 20 rounds) with all key material as immediates.
// Returns o0 ^ o1 (partitionable bits fold).
// ---------------------------------------------------------------------------
template<unsigned A0,unsigned B0,unsigned A1,unsigned B1,unsigned A2,unsigned B2,
         unsigned A3,unsigned B3,unsigned A4,unsigned B4,unsigned A5,unsigned B5>
__device__ __forceinline__ unsigned tf_bits(unsigned c1, unsigned one) {
    unsigned x1 = addimm<B0>(c1, one);
    unsigned x0 = addimm<A0>(x1, one);   // round-1 add folded with x0 init
    x1 = __funnelshift_l(x1, x1, 13); x1 ^= x0;
#define TFR(r) { x0 = addf(x1, x0, one); \
                 x1 = __funnelshift_l(x1, x1, (r)); x1 ^= x0; }
    TFR(15) TFR(26) TFR(6)
    x0 = addimm<A1>(x0, one); x1 = addimm<B1>(x1, one);
    TFR(17) TFR(29) TFR(16) TFR(24)
    x0 = addimm<A2>(x0, one); x1 = addimm<B2>(x1, one);
    TFR(13) TFR(15) TFR(26) TFR(6)
    x0 = addimm<A3>(x0, one); x1 = addimm<B3>(x1, one);
    TFR(17) TFR(29) TFR(16) TFR(24)
    x0 = addimm<A4>(x0, one); x1 = addimm<B4>(x1, one);
    TFR(13) TFR(15) TFR(26) TFR(6)
    x0 = addimm<A5>(x0, one); x1 = addimm<B5>(x1, one);
#undef TFR
    return x0 ^ x1;
}

// ---------------------------------------------------------------------------
// Clampless predicated Bernoulli tail (R13 order — measured optimal):
//   setp.lt sp, u, p      — spike decision
//   selp    oval          — pred-as-data (4 cyc), fills the 13-cyc
//                           pred-as-guard window before @sp is consumed
//   @sp add rem, rem, -1  — unclamped rem update (exact)
// clip removal validated bit-exactly by R12 (rel_err == 0.0 on full dataset);
// the R15/R16 experiment showed reordering @sp add earlier exposes the
// guard latency on the carried chain (+6 us) — this order is final.
// ---------------------------------------------------------------------------
__device__ __forceinline__ float bern_tail(float& rem, float u, float p,
                                           float ov0, float ov1) {
    float oval;
    asm("{\n\t"
        ".reg .pred sp;\n\t"
        "setp.lt.f32 sp, %2, %3;\n\t"
        "selp.f32 %0, %4, %5, sp;\n\t"
        "@sp add.f32 %1, %1, 0fBF800000;\n\t"    // rem -= 1 (exact)
        "}"
        : "=f"(oval), "+f"(rem)
        : "f"(u), "f"(p), "f"(ov1), "f"(ov0));
    return oval;
}

// ---------------------------------------------------------------------------
// One fully specialized time step for 4 elements. The 4 threefry blocks are
// computed first (independent chains), then the float tail.
// ---------------------------------------------------------------------------
template<int T>
__device__ __forceinline__ void do_step(float rem[EPT], unsigned j,
                                        float ov0, float ov1,
                                        unsigned one, unsigned c23,
                                        float* __restrict__ out)
{
    constexpr int   S    = TSTEPS - T;            // remaining slots
    constexpr float SF   = (float)S;
    constexpr float INV  = 1.0f / SF;             // rn(1/S), exact for pow2
    constexpr bool  POW2 = (S & (S - 1)) == 0;
    constexpr Keys  K    = make_keys(T);

    unsigned bits[EPT];
#pragma unroll
    for (int e = 0; e < EPT; e++) {
        bits[e] = tf_bits<K.a0,K.b0,K.a1,K.b1,K.a2,K.b2,
                          K.a3,K.b3,K.a4,K.b4,K.a5,K.b5>(j + (unsigned)e, one);
    }

    float ovals[EPT];
#pragma unroll
    for (int e = 0; e < EPT; e++) {
        // u = bitcast((bits>>9)|0x3f800000) - 1.0 (exact Sterbenz subtraction)
        const float u = __uint_as_float(ubits(bits[e], c23)) - 1.0f;

        // p = rn(rem/S). Reference's clip(p,0,1) drops out (R12-validated).
        float p;
        if (S == 1) {
            p = rem[e];
        } else if (POW2) {
            p = __fmul_rn(rem[e], INV);
        } else {
            const float q0 = __fmul_rn(rem[e], INV);
            const float r  = __fmaf_rn(-SF, q0, rem[e]);
            p = __fmaf_rn(r, INV, q0);            // Markstein, correctly rounded
        }

        if (S > 1) {
            ovals[e] = bern_tail(rem[e], u, p, ov0, ov1);
        } else {
            ovals[e] = (u < p) ? ov1 : ov0;       // last step: rem is dead
        }
    }

    float4 o;
    o.x = ovals[0]; o.y = ovals[1]; o.z = ovals[2]; o.w = ovals[3];
    // Streaming store: output is write-once, never re-read.
    __stcs(reinterpret_cast<float4*>(out + (size_t)T * NELEM + j), o);
}

// ---------------------------------------------------------------------------
// Main kernel. __launch_bounds__(256, 4): 64-reg budget (proven equal-best).
// Grid covers NELEM exactly, so no bounds guard. R13 structure throughout.
// ---------------------------------------------------------------------------
__global__ void __launch_bounds__(256, 4)
hyper_kernel(const float* __restrict__ x,
             const float* __restrict__ meanv,
             const float* __restrict__ stdv,
             float* __restrict__ out,
             unsigned one, unsigned c23)
{
    const unsigned j = (blockIdx.x * blockDim.x + threadIdx.x) * EPT;

    const unsigned c = (j / HWPLANE) % 3u;
    const float m = meanv[c];
    const float s = stdv[c];
    // Output values for spike=0 and spike=1: (spike - m) / s, IEEE divide.
    const float ov0 = __fdiv_rn(0.0f - m, s);
    const float ov1 = __fdiv_rn(1.0f - m, s);

    const float4 xv = *reinterpret_cast<const float4*>(x + j);

    // probs = clip(x*s + m, 0, 1) (separate rn mul + rn add, matching XLA);
    // rem0 = probs * 16 (exact).
    float rem[EPT];
    {
        const float xs[EPT] = {xv.x, xv.y, xv.z, xv.w};
#pragma unroll
        for (int e = 0; e < EPT; e++) {
            float pr = __fadd_rn(__fmul_rn(xs[e], s), m);
            pr = fminf(fmaxf(pr, 0.0f), 1.0f);
            rem[e] = __fmul_rn(pr, 16.0f);
        }
    }

    do_step< 0>(rem, j, ov0, ov1, one, c23, out);
    do_step< 1>(rem, j, ov0, ov1, one, c23, out);
    do_step< 2>(rem, j, ov0, ov1, one, c23, out);
    do_step< 3>(rem, j, ov0, ov1, one, c23, out);
    do_step< 4>(rem, j, ov0, ov1, one, c23, out);
    do_step< 5>(rem, j, ov0, ov1, one, c23, out);
    do_step< 6>(rem, j, ov0, ov1, one, c23, out);
    do_step< 7>(rem, j, ov0, ov1, one, c23, out);
    do_step< 8>(rem, j, ov0, ov1, one, c23, out);
    do_step< 9>(rem, j, ov0, ov1, one, c23, out);
    do_step<10>(rem, j, ov0, ov1, one, c23, out);
    do_step<11>(rem, j, ov0, ov1, one, c23, out);
    do_step<12>(rem, j, ov0, ov1, one, c23, out);
    do_step<13>(rem, j, ov0, ov1, one, c23, out);
    do_step<14>(rem, j, ov0, ov1, one, c23, out);
    do_step<15>(rem, j, ov0, ov1, one, c23, out);
}

// ---------------------------------------------------------------------------
// Launch: single kernel, graph-capturable, allocation-free. The opaque
// 'one'/'c23' params keep the IMAD forms alive through ptxas.
// ---------------------------------------------------------------------------
extern "C" void kernel_launch(void* const* d_in, const int* in_sizes, int n_in,
                              void* d_out, int out_size) {
    (void)in_sizes; (void)n_in; (void)out_size;

    const float* x  = (const float*)d_in[0];
    const float* mn = (const float*)d_in[1];
    const float* sd = (const float*)d_in[2];
    float* out = (float*)d_out;

    const int threads = 256;
    const int blocks = NELEM / (threads * EPT);   // 9408 exactly
    hyper_kernel<<<blocks, threads>>>(x, mn, sd, out, 1u, 1u << 23);
}